// round 15
// baseline (speedup 1.0000x reference)
#include <cuda_runtime.h>
#include <cstdint>

// SSIM loss, fully fused — horizontal-first separable blur, f32x2 row-pair packing.
// Round 15: BARRIER-FREE warp-private pipelines. Each warp owns 32 output columns,
// loads its own 42-col halo via per-thread cp.async groups, double-buffered smem,
// CP_WAIT(1)+__syncwarp() only. No __syncthreads in the main loop; warps de-phase.

#define IMG_H 1024
#define IMG_W 1024
#define EW    128          // blockDim.x (4 warps x 32 output cols = 128 cols/CTA)
#define ROWS  205          // 5 * 205 = 1025 >= 1024 (tail guarded)
#define GRID_Y 5
#define CHUNK 12
#define NCHUNKS ((ROWS + CHUNK - 1) / CHUNK)      // 18
#define NBLK  (8 * GRID_Y * 16)                   // 640
#define WC 42              // extended cols per warp (32 + 2*5)

typedef unsigned long long u64;

__device__ double g_acc = 0.0;
__device__ unsigned int g_cnt = 0u;

__device__ __forceinline__ u64 fma2(u64 a, u64 b, u64 c) {
    u64 d; asm("fma.rn.f32x2 %0, %1, %2, %3;" : "=l"(d) : "l"(a), "l"(b), "l"(c)); return d;
}
__device__ __forceinline__ u64 mul2(u64 a, u64 b) {
    u64 d; asm("mul.rn.f32x2 %0, %1, %2;" : "=l"(d) : "l"(a), "l"(b)); return d;
}
__device__ __forceinline__ u64 add2(u64 a, u64 b) {
    u64 d; asm("add.rn.f32x2 %0, %1, %2;" : "=l"(d) : "l"(a), "l"(b)); return d;
}
__device__ __forceinline__ u64 sub2(u64 a, u64 b) {
    u64 d; asm("sub.rn.f32x2 %0, %1, %2;" : "=l"(d) : "l"(a), "l"(b)); return d;
}
__device__ __forceinline__ u64 pack2(float lo, float hi) {
    u64 d; asm("mov.b64 %0, {%1, %2};" : "=l"(d) : "f"(lo), "f"(hi)); return d;
}
__device__ __forceinline__ void unpack2(u64 v, float& lo, float& hi) {
    asm("mov.b64 {%0, %1}, %2;" : "=f"(lo), "=f"(hi) : "l"(v));
}
__device__ __forceinline__ void cpa4(uint32_t dst, const float* src, unsigned sz) {
    asm volatile("cp.async.ca.shared.global [%0], [%1], 4, %2;"
                 :: "r"(dst), "l"(src), "r"(sz));
}
#define CP_COMMIT() asm volatile("cp.async.commit_group;" ::: "memory")
#define CP_WAIT(n)  asm volatile("cp.async.wait_group %0;" :: "n"(n) : "memory")

// per-pair compute: taps k read swp[(J)*WC + lane + k]; GUARD is a 0/1 literal
#define PAIR_COMPUTE(SWP, J, GUARD) do {                                            \
  if (!(GUARD) || (rb + 2 * (J) < ROWS)) {                                          \
    u64 h1, h2, h3a, h3b, h5;                                                       \
    {                                                                               \
      const float4 t4 = (SWP)[(J) * WC + lane];                                     \
      const u64 A = *(const u64*)&t4.x;                                             \
      const u64 B = *(const u64*)&t4.z;                                             \
      const u64 w = KW2(0);                                                         \
      const u64 ta = mul2(w, A);                                                    \
      const u64 tb = mul2(w, B);                                                    \
      h1 = ta; h2 = tb;                                                             \
      h3a = mul2(ta, A); h3b = mul2(tb, B); h5 = mul2(ta, B);                       \
    }                                                                               \
    _Pragma("unroll")                                                               \
    for (int k = 1; k < 11; ++k) {                                                  \
      const float4 t4 = (SWP)[(J) * WC + lane + k];                                 \
      const u64 A = *(const u64*)&t4.x;                                             \
      const u64 B = *(const u64*)&t4.z;                                             \
      const u64 w = KW2(k);                                                         \
      const u64 ta = mul2(w, A);                                                    \
      const u64 tb = mul2(w, B);                                                    \
      h1 = add2(h1, ta);                                                            \
      h2 = add2(h2, tb);                                                            \
      h3a = fma2(ta, A, h3a);                                                       \
      h3b = fma2(tb, B, h3b);                                                       \
      h5 = fma2(ta, B, h5);                                                         \
    }                                                                               \
    const u64 h3 = add2(h3a, h3b);                                                  \
    unpack2(h1, v1[(2*(J)+10)%12], v1[(2*(J)+11)%12]);                              \
    unpack2(h2, v2[(2*(J)+10)%12], v2[(2*(J)+11)%12]);                              \
    unpack2(h3, v3[(2*(J)+10)%12], v3[(2*(J)+11)%12]);                              \
    unpack2(h5, v5[(2*(J)+10)%12], v5[(2*(J)+11)%12]);                              \
    float m1q0, m2q0, m3q0, m5q0, m1q1, m2q1, m3q1, m5q1;                           \
    { float m1=0.f, m2=0.f, m3=0.f, m5=0.f;                                         \
      _Pragma("unroll")                                                             \
      for (int d = 0; d < 11; ++d) {                                                \
        const int s = (2*(J) + d) % 12;                                             \
        m1 = fmaf(KW[d], v1[s], m1); m2 = fmaf(KW[d], v2[s], m2);                   \
        m3 = fmaf(KW[d], v3[s], m3); m5 = fmaf(KW[d], v5[s], m5); }                 \
      m1q0=m1; m2q0=m2; m3q0=m3; m5q0=m5; }                                         \
    { float m1=0.f, m2=0.f, m3=0.f, m5=0.f;                                         \
      _Pragma("unroll")                                                             \
      for (int d = 0; d < 11; ++d) {                                                \
        const int s = (2*(J) + 1 + d) % 12;                                         \
        m1 = fmaf(KW[d], v1[s], m1); m2 = fmaf(KW[d], v2[s], m2);                   \
        m3 = fmaf(KW[d], v3[s], m3); m5 = fmaf(KW[d], v5[s], m5); }                 \
      m1q1=m1; m2q1=m2; m3q1=m3; m5q1=m5; }                                         \
    const u64 M1 = pack2(m1q0, m1q1), M2 = pack2(m2q0, m2q1);                       \
    const u64 M3 = pack2(m3q0, m3q1), M5 = pack2(m5q0, m5q1);                       \
    const u64 MU12 = mul2(M1, M2);                                                  \
    const u64 T    = add2(mul2(M1, M1), mul2(M2, M2));                              \
    const u64 NUM  = mul2(fma2(TW2, MU12, C1V), fma2(TW2, sub2(M5, MU12), C2V));    \
    const u64 DEN  = mul2(add2(T, C1V), add2(sub2(M3, T), C2V));                    \
    float n0, n1, d0, d1; unpack2(NUM, n0, n1); unpack2(DEN, d0, d1);               \
    if (!(GUARD)) {                                                                 \
      acc += __fdividef(fmaf(n0, d1, n1 * d0), d0 * d1);                            \
    } else {                                                                        \
      if (y0 + rb + 2*(J)     < IMG_H) acc += __fdividef(n0, d0);                   \
      if (y0 + rb + 2*(J) + 1 < IMG_H) acc += __fdividef(n1, d1);                   \
    }                                                                               \
  } } while (0)

__global__ __launch_bounds__(EW, 5) void ssim_kernel(const float* __restrict__ img1,
                                                     const float* __restrict__ img2,
                                                     float* __restrict__ out) {
    const float KW[11] = {
        0.0010283853f, 0.0075987626f, 0.0360007730f, 0.1093606900f,
        0.2130055300f, 0.2660117200f, 0.2130055300f, 0.1093606900f,
        0.0360007730f, 0.0075987626f, 0.0010283853f
    };
    u64 kw2[6];
    #pragma unroll
    for (int k = 0; k < 6; ++k) kw2[k] = pack2(KW[k], KW[k]);
#define KW2(k) kw2[(k) < 6 ? (k) : 10 - (k)]

    const unsigned c1b = __float_as_uint(0.0001f);
    const unsigned c2b = __float_as_uint(0.0009f);
    const unsigned twb = __float_as_uint(2.0f);
    const u64 C1V = ((u64)c1b << 32) | c1b;
    const u64 C2V = ((u64)c2b << 32) | c2b;
    const u64 TW2 = ((u64)twb << 32) | twb;

    const int tid  = threadIdx.x;
    const int wid  = tid >> 5;
    const int lane = tid & 31;
    const size_t base = (size_t)blockIdx.z * (size_t)(IMG_H * IMG_W);
    const int y0 = blockIdx.y * ROWS;

    // this thread's two halo columns (col-1 only for lane < 10)
    const int gc0 = blockIdx.x * 128 + wid * 32 - 5 + lane;
    const int gc1 = gc0 + 32;
    const unsigned sz0 = (gc0 >= 0 && gc0 < IMG_W) ? 4u : 0u;
    const unsigned sz1 = (gc1 < IMG_W) ? 4u : 0u;        // gc1 >= 27 always
    const bool has2 = (lane < 10);
    const float* p1  = img1 + base + gc0;
    const float* p2  = img2 + base + gc0;

    __shared__ float4 sw[2][4][6][WC];   // [slot][warp][pair][ecol] = 31.5 KB
    __shared__ float red[4];

    uint32_t sb;
    asm("{ .reg .u64 t; cvta.to.shared.u64 t, %1; cvt.u32.u64 %0, t; }"
        : "=r"(sb) : "l"((void*)&sw[0][0][0][0]));
    // byte offsets: slot*16128 + wid*4032 + j*672 + i*16
    const uint32_t my0 = sb + (uint32_t)(wid * 4032 + lane * 16);
    const uint32_t my1 = my0 + 512u;     // lane+32

    float v1[12], v2[12], v3[12], v5[12];
    float acc = 0.f;

    // ---------- issue prime (5 pairs -> slot 1) and chunk 0 (6 pairs -> slot 0) ----------
    #pragma unroll
    for (int i = 0; i < 5; ++i) {
        const int r0 = y0 - 5 + 2 * i, r1 = r0 + 1;
        const unsigned s0a = (r0 >= 0) ? sz0 : 0u;
        const unsigned s0b = (r1 >= 0) ? sz0 : 0u;
        const uint32_t d = my0 + 16128u + (uint32_t)i * 672u;
        cpa4(d,        p1 + (size_t)r0 * IMG_W, s0a);
        cpa4(d + 4u,   p1 + (size_t)r1 * IMG_W, s0b);
        cpa4(d + 8u,   p2 + (size_t)r0 * IMG_W, s0a);
        cpa4(d + 12u,  p2 + (size_t)r1 * IMG_W, s0b);
        if (has2) {
            const unsigned s1a = (r0 >= 0) ? sz1 : 0u;
            const unsigned s1b = (r1 >= 0) ? sz1 : 0u;
            const uint32_t e = my1 + 16128u + (uint32_t)i * 672u;
            cpa4(e,        p1 + (size_t)r0 * IMG_W + 32, s1a);
            cpa4(e + 4u,   p1 + (size_t)r1 * IMG_W + 32, s1b);
            cpa4(e + 8u,   p2 + (size_t)r0 * IMG_W + 32, s1a);
            cpa4(e + 12u,  p2 + (size_t)r1 * IMG_W + 32, s1b);
        }
    }
    CP_COMMIT();
    #pragma unroll
    for (int j = 0; j < 6; ++j) {        // rows y0+5..y0+16, always < IMG_H (y0 <= 820)
        const int r0 = y0 + 5 + 2 * j, r1 = r0 + 1;
        const uint32_t d = my0 + (uint32_t)j * 672u;
        cpa4(d,        p1 + (size_t)r0 * IMG_W, sz0);
        cpa4(d + 4u,   p1 + (size_t)r1 * IMG_W, sz0);
        cpa4(d + 8u,   p2 + (size_t)r0 * IMG_W, sz0);
        cpa4(d + 12u,  p2 + (size_t)r1 * IMG_W, sz0);
        if (has2) {
            const uint32_t e = my1 + (uint32_t)j * 672u;
            cpa4(e,        p1 + (size_t)r0 * IMG_W + 32, sz1);
            cpa4(e + 4u,   p1 + (size_t)r1 * IMG_W + 32, sz1);
            cpa4(e + 8u,   p2 + (size_t)r0 * IMG_W + 32, sz1);
            cpa4(e + 12u,  p2 + (size_t)r1 * IMG_W + 32, sz1);
        }
    }
    CP_COMMIT();
    CP_WAIT(1);            // prime landed; chunk 0 may be in flight
    __syncwarp();

    // ---------- prime horizontal: 5 pairs (slot 1) -> ring 0..9 ----------
    {
        const float4* swp1 = &sw[1][wid][0][0];
        #pragma unroll
        for (int i = 0; i < 5; ++i) {
            u64 h1, h2, h3a, h3b, h5;
            {
                const float4 t4 = swp1[i * WC + lane];
                const u64 A = *(const u64*)&t4.x;
                const u64 B = *(const u64*)&t4.z;
                const u64 w = KW2(0);
                const u64 ta = mul2(w, A);
                const u64 tb = mul2(w, B);
                h1 = ta; h2 = tb;
                h3a = mul2(ta, A); h3b = mul2(tb, B); h5 = mul2(ta, B);
            }
            #pragma unroll
            for (int k = 1; k < 11; ++k) {
                const float4 t4 = swp1[i * WC + lane + k];
                const u64 A = *(const u64*)&t4.x;
                const u64 B = *(const u64*)&t4.z;
                const u64 w = KW2(k);
                const u64 ta = mul2(w, A);
                const u64 tb = mul2(w, B);
                h1 = add2(h1, ta);
                h2 = add2(h2, tb);
                h3a = fma2(ta, A, h3a);
                h3b = fma2(tb, B, h3b);
                h5 = fma2(ta, B, h5);
            }
            const u64 h3 = add2(h3a, h3b);
            unpack2(h1, v1[2*i], v1[2*i+1]);
            unpack2(h2, v2[2*i], v2[2*i+1]);
            unpack2(h3, v3[2*i], v3[2*i+1]);
            unpack2(h5, v5[2*i], v5[2*i+1]);
        }
    }
    v1[10] = v2[10] = v3[10] = v5[10] = 0.f;
    v1[11] = v2[11] = v3[11] = v5[11] = 0.f;

    // advanced prefetch pointers (chunk 1 rows start at y0 + 17)
    const float* q1 = p1 + (size_t)(y0 + CHUNK + 5) * IMG_W;
    const float* q2 = p2 + (size_t)(y0 + CHUNK + 5) * IMG_W;

    // ---------- main loop: per-warp pipeline, NO block barriers ----------
    for (int c = 0; c < NCHUNKS; ++c) {
        const int rb = c * CHUNK;

        if (c + 1 < NCHUNKS) {
            const int rb2 = rb + CHUNK;
            const uint32_t d0base = my0 + (uint32_t)(((c + 1) & 1) * 16128);
            const uint32_t d1base = my1 + (uint32_t)(((c + 1) & 1) * 16128);
            if (y0 + rb2 + 16 < IMG_H) {
                #pragma unroll
                for (int j = 0; j < 6; ++j) {
                    const uint32_t d = d0base + (uint32_t)j * 672u;
                    cpa4(d,        q1 + j * 2048,        sz0);
                    cpa4(d + 4u,   q1 + j * 2048 + 1024, sz0);
                    cpa4(d + 8u,   q2 + j * 2048,        sz0);
                    cpa4(d + 12u,  q2 + j * 2048 + 1024, sz0);
                }
                if (has2) {
                    #pragma unroll
                    for (int j = 0; j < 6; ++j) {
                        const uint32_t e = d1base + (uint32_t)j * 672u;
                        cpa4(e,        q1 + j * 2048 + 32,   sz1);
                        cpa4(e + 4u,   q1 + j * 2048 + 1056, sz1);
                        cpa4(e + 8u,   q2 + j * 2048 + 32,   sz1);
                        cpa4(e + 12u,  q2 + j * 2048 + 1056, sz1);
                    }
                }
            } else {
                #pragma unroll
                for (int j = 0; j < 6; ++j) {
                    if (rb2 + 2 * j < ROWS) {
                        const int r0 = y0 + rb2 + 5 + 2 * j, r1 = r0 + 1;
                        const unsigned s0a = (r0 < IMG_H) ? sz0 : 0u;
                        const unsigned s0b = (r1 < IMG_H) ? sz0 : 0u;
                        const uint32_t d = d0base + (uint32_t)j * 672u;
                        cpa4(d,        p1 + (size_t)r0 * IMG_W, s0a);
                        cpa4(d + 4u,   p1 + (size_t)r1 * IMG_W, s0b);
                        cpa4(d + 8u,   p2 + (size_t)r0 * IMG_W, s0a);
                        cpa4(d + 12u,  p2 + (size_t)r1 * IMG_W, s0b);
                        if (has2) {
                            const unsigned s1a = (r0 < IMG_H) ? sz1 : 0u;
                            const unsigned s1b = (r1 < IMG_H) ? sz1 : 0u;
                            const uint32_t e = d1base + (uint32_t)j * 672u;
                            cpa4(e,        p1 + (size_t)r0 * IMG_W + 32, s1a);
                            cpa4(e + 4u,   p1 + (size_t)r1 * IMG_W + 32, s1b);
                            cpa4(e + 8u,   p2 + (size_t)r0 * IMG_W + 32, s1a);
                            cpa4(e + 12u,  p2 + (size_t)r1 * IMG_W + 32, s1b);
                        }
                    }
                }
            }
            CP_COMMIT();
            CP_WAIT(1);    // chunk c's group complete; chunk c+1 in flight
        } else {
            CP_WAIT(0);
        }
        q1 += CHUNK * IMG_W;
        q2 += CHUNK * IMG_W;
        __syncwarp();      // warp-scope visibility of this chunk's async stores

        const float4* swp = &sw[c & 1][wid][0][0];
        if ((rb + 11 < ROWS) && (y0 + rb + 11 < IMG_H)) {
            #pragma unroll
            for (int j = 0; j < 6; ++j) { PAIR_COMPUTE(swp, j, 0); }
        } else {
            #pragma unroll
            for (int j = 0; j < 6; ++j) { PAIR_COMPUTE(swp, j, 1); }
        }
        __syncwarp();      // all lanes done reading slot (c&1) before next overwrite
    }

    // ---------- reduction (single final block barrier) + last-block finalize ----------
    #pragma unroll
    for (int o = 16; o; o >>= 1) acc += __shfl_xor_sync(0xffffffffu, acc, o);
    if (lane == 0) red[wid] = acc;
    __syncthreads();
    if (tid == 0) {
        const double t = (double)(red[0] + red[1] + red[2] + red[3]);
        atomicAdd(&g_acc, t);
        __threadfence();
        const unsigned int n = atomicAdd(&g_cnt, 1u);
        if (n == NBLK - 1) {
            const double total = atomicAdd(&g_acc, 0.0);
            out[0] = (float)(1.0 - total / 16777216.0);
            atomicExch((unsigned long long*)&g_acc, 0ull);
            atomicExch(&g_cnt, 0u);
        }
    }
}

extern "C" void kernel_launch(void* const* d_in, const int* in_sizes, int n_in,
                              void* d_out, int out_size) {
    const float* img1 = (const float*)d_in[0];
    const float* img2 = (const float*)d_in[1];
    float* out = (float*)d_out;

    dim3 grid(IMG_W / 128, GRID_Y, 16);  // (8, 5, 16) = 640 CTAs
    ssim_kernel<<<grid, EW>>>(img1, img2, out);
}

// round 16
// speedup vs baseline: 1.1650x; 1.1650x over previous
#include <cuda_runtime.h>
#include <cstdint>

// SSIM loss, fully fused — horizontal-first separable blur, f32x2 row-pair packing,
// LDS.128 interleaved smem, cp.async triple-buffered pipeline, block barriers
// (round-14 core). Round 16: full-width CTAs — 128 output cols computed by all 128
// threads; 10 halo cols loaded by threads 0-9 via constant-offset extra copies.
// Grid (8,8,16)=1024 CTAs, ROWS=128: per-SM quantized work 966 vs 1055 row-units.

#define IMG_H 1024
#define IMG_W 1024
#define EW    128          // blockDim.x == output cols per CTA
#define ROWS  128
#define CHUNK 12
#define NCHUNKS ((ROWS + CHUNK - 1) / CHUNK)      // 11 (last chunk: 8 rows)
#define NBLK  (8 * 8 * 16)                        // 1024
#define ECOLS 138          // 128 + 2*5 halo
#define PSTR  2208u        // pair stride bytes   (138*16)
#define SSTR  13248u       // slot stride bytes   (6*2208)

typedef unsigned long long u64;

__device__ double g_acc = 0.0;
__device__ unsigned int g_cnt = 0u;

__device__ __forceinline__ u64 fma2(u64 a, u64 b, u64 c) {
    u64 d; asm("fma.rn.f32x2 %0, %1, %2, %3;" : "=l"(d) : "l"(a), "l"(b), "l"(c)); return d;
}
__device__ __forceinline__ u64 mul2(u64 a, u64 b) {
    u64 d; asm("mul.rn.f32x2 %0, %1, %2;" : "=l"(d) : "l"(a), "l"(b)); return d;
}
__device__ __forceinline__ u64 add2(u64 a, u64 b) {
    u64 d; asm("add.rn.f32x2 %0, %1, %2;" : "=l"(d) : "l"(a), "l"(b)); return d;
}
__device__ __forceinline__ u64 sub2(u64 a, u64 b) {
    u64 d; asm("sub.rn.f32x2 %0, %1, %2;" : "=l"(d) : "l"(a), "l"(b)); return d;
}
__device__ __forceinline__ u64 pack2(float lo, float hi) {
    u64 d; asm("mov.b64 %0, {%1, %2};" : "=l"(d) : "f"(lo), "f"(hi)); return d;
}
__device__ __forceinline__ void unpack2(u64 v, float& lo, float& hi) {
    asm("mov.b64 {%0, %1}, %2;" : "=f"(lo), "=f"(hi) : "l"(v));
}
__device__ __forceinline__ void cpa4(uint32_t dst, const float* src, unsigned sz) {
    asm volatile("cp.async.ca.shared.global [%0], [%1], 4, %2;"
                 :: "r"(dst), "l"(src), "r"(sz));
}
#define CP_COMMIT() asm volatile("cp.async.commit_group;" ::: "memory")
#define CP_WAIT(n)  asm volatile("cp.async.wait_group %0;" :: "n"(n) : "memory")

// per-pair compute; GUARD is 0/1 literal. Reads sab4 flat: [slot][j*138 + tid + k].
#define PAIR_COMPUTE(SWP, J, GUARD) do {                                            \
  if (!(GUARD) || (rb + 2 * (J) < ROWS)) {                                          \
    u64 h1, h2, h3a, h3b, h5;                                                       \
    {                                                                               \
      const float4 t4 = (SWP)[(J) * ECOLS + tid];                                   \
      const u64 A = *(const u64*)&t4.x;                                             \
      const u64 B = *(const u64*)&t4.z;                                             \
      const u64 w = KW2(0);                                                         \
      const u64 ta = mul2(w, A);                                                    \
      const u64 tb = mul2(w, B);                                                    \
      h1 = ta; h2 = tb;                                                             \
      h3a = mul2(ta, A); h3b = mul2(tb, B); h5 = mul2(ta, B);                       \
    }                                                                               \
    _Pragma("unroll")                                                               \
    for (int k = 1; k < 11; ++k) {                                                  \
      const float4 t4 = (SWP)[(J) * ECOLS + tid + k];                               \
      const u64 A = *(const u64*)&t4.x;                                             \
      const u64 B = *(const u64*)&t4.z;                                             \
      const u64 w = KW2(k);                                                         \
      const u64 ta = mul2(w, A);                                                    \
      const u64 tb = mul2(w, B);                                                    \
      h1 = add2(h1, ta);                                                            \
      h2 = add2(h2, tb);                                                            \
      h3a = fma2(ta, A, h3a);                                                       \
      h3b = fma2(tb, B, h3b);                                                       \
      h5 = fma2(ta, B, h5);                                                         \
    }                                                                               \
    const u64 h3 = add2(h3a, h3b);                                                  \
    unpack2(h1, v1[(2*(J)+10)%12], v1[(2*(J)+11)%12]);                              \
    unpack2(h2, v2[(2*(J)+10)%12], v2[(2*(J)+11)%12]);                              \
    unpack2(h3, v3[(2*(J)+10)%12], v3[(2*(J)+11)%12]);                              \
    unpack2(h5, v5[(2*(J)+10)%12], v5[(2*(J)+11)%12]);                              \
    float m1q0, m2q0, m3q0, m5q0, m1q1, m2q1, m3q1, m5q1;                           \
    { float m1=0.f, m2=0.f, m3=0.f, m5=0.f;                                         \
      _Pragma("unroll")                                                             \
      for (int d = 0; d < 11; ++d) {                                                \
        const int s = (2*(J) + d) % 12;                                             \
        m1 = fmaf(KW[d], v1[s], m1); m2 = fmaf(KW[d], v2[s], m2);                   \
        m3 = fmaf(KW[d], v3[s], m3); m5 = fmaf(KW[d], v5[s], m5); }                 \
      m1q0=m1; m2q0=m2; m3q0=m3; m5q0=m5; }                                         \
    { float m1=0.f, m2=0.f, m3=0.f, m5=0.f;                                         \
      _Pragma("unroll")                                                             \
      for (int d = 0; d < 11; ++d) {                                                \
        const int s = (2*(J) + 1 + d) % 12;                                         \
        m1 = fmaf(KW[d], v1[s], m1); m2 = fmaf(KW[d], v2[s], m2);                   \
        m3 = fmaf(KW[d], v3[s], m3); m5 = fmaf(KW[d], v5[s], m5); }                 \
      m1q1=m1; m2q1=m2; m3q1=m3; m5q1=m5; }                                         \
    const u64 M1 = pack2(m1q0, m1q1), M2 = pack2(m2q0, m2q1);                       \
    const u64 M3 = pack2(m3q0, m3q1), M5 = pack2(m5q0, m5q1);                       \
    const u64 MU12 = mul2(M1, M2);                                                  \
    const u64 T    = add2(mul2(M1, M1), mul2(M2, M2));                              \
    const u64 NUM  = mul2(fma2(TW2, MU12, C1V), fma2(TW2, sub2(M5, MU12), C2V));    \
    const u64 DEN  = mul2(add2(T, C1V), add2(sub2(M3, T), C2V));                    \
    float n0, n1, d0, d1; unpack2(NUM, n0, n1); unpack2(DEN, d0, d1);               \
    acc += __fdividef(fmaf(n0, d1, n1 * d0), d0 * d1);                              \
  } } while (0)

__global__ __launch_bounds__(EW, 5) void ssim_kernel(const float* __restrict__ img1,
                                                     const float* __restrict__ img2,
                                                     float* __restrict__ out) {
    const float KW[11] = {
        0.0010283853f, 0.0075987626f, 0.0360007730f, 0.1093606900f,
        0.2130055300f, 0.2660117200f, 0.2130055300f, 0.1093606900f,
        0.0360007730f, 0.0075987626f, 0.0010283853f
    };
    u64 kw2[6];
    #pragma unroll
    for (int k = 0; k < 6; ++k) kw2[k] = pack2(KW[k], KW[k]);
#define KW2(k) kw2[(k) < 6 ? (k) : 10 - (k)]

    const unsigned c1b = __float_as_uint(0.0001f);
    const unsigned c2b = __float_as_uint(0.0009f);
    const unsigned twb = __float_as_uint(2.0f);
    const u64 C1V = ((u64)c1b << 32) | c1b;
    const u64 C2V = ((u64)c2b << 32) | c2b;
    const u64 TW2 = ((u64)twb << 32) | twb;

    const int tid = threadIdx.x;
    const size_t base = (size_t)blockIdx.z * (size_t)(IMG_H * IMG_W);
    const int y0  = blockIdx.y * ROWS;
    const int col = blockIdx.x * EW + tid;           // always in [0, 1023]
    const float* p1 = img1 + base + col;
    const float* p2 = img2 + base + col;

    // halo: threads 0-9 also load one extra column at constant offset hd from col.
    //   tid<5  -> ecol = tid       (col-5)   hd = -5
    //   5<=tid<10 -> ecol = tid+128 (col+123) hd = +123
    const bool hhalo = (tid < 10);
    const int  hd    = (tid < 5) ? -5 : 123;
    const int  hcol  = col + hd;
    const unsigned hsz = (hhalo && hcol >= 0 && hcol < IMG_W) ? 4u : 0u;
    const uint32_t hecol = (tid < 5) ? (uint32_t)tid : (uint32_t)(tid + 128);

    __shared__ float4 sab4[3][6][ECOLS];   // interleaved {a_r0,a_r1,b_r0,b_r1}: ~39 KB
    __shared__ float red[4];

    uint32_t sb;
    asm("{ .reg .u64 t; cvta.to.shared.u64 t, %1; cvt.u32.u64 %0, t; }"
        : "=r"(sb) : "l"((void*)&sab4[0][0][0]));
    const uint32_t sbt = sb + (uint32_t)(tid + 5) * 16u;   // main ecol = tid+5
    const uint32_t sbh = sb + hecol * 16u;                 // halo ecol

    float v1[12], v2[12], v3[12], v5[12];
    float acc = 0.f;

    // ---------- issue prime (5 pairs -> slot 2) and chunk 0 (6 pairs -> slot 0) ----------
    #pragma unroll
    for (int i = 0; i < 5; ++i) {
        const int r0 = y0 - 5 + 2 * i, r1 = r0 + 1;
        const unsigned sa = (r0 >= 0) ? 4u : 0u;
        const unsigned sbv = (r1 >= 0) ? 4u : 0u;
        const uint32_t d = sbt + 2u * SSTR + (uint32_t)i * PSTR;
        cpa4(d,        p1 + (size_t)r0 * IMG_W, sa);
        cpa4(d + 4u,   p1 + (size_t)r1 * IMG_W, sbv);
        cpa4(d + 8u,   p2 + (size_t)r0 * IMG_W, sa);
        cpa4(d + 12u,  p2 + (size_t)r1 * IMG_W, sbv);
        if (hhalo) {
            const unsigned ha = (r0 >= 0) ? hsz : 0u;
            const unsigned hb = (r1 >= 0) ? hsz : 0u;
            const uint32_t e = sbh + 2u * SSTR + (uint32_t)i * PSTR;
            cpa4(e,        p1 + (size_t)r0 * IMG_W + hd, ha);
            cpa4(e + 4u,   p1 + (size_t)r1 * IMG_W + hd, hb);
            cpa4(e + 8u,   p2 + (size_t)r0 * IMG_W + hd, ha);
            cpa4(e + 12u,  p2 + (size_t)r1 * IMG_W + hd, hb);
        }
    }
    CP_COMMIT();
    #pragma unroll
    for (int j = 0; j < 6; ++j) {      // rows y0+5..y0+16; y0 <= 896 -> max 912 < 1024
        const int r0 = y0 + 5 + 2 * j, r1 = r0 + 1;
        const uint32_t d = sbt + (uint32_t)j * PSTR;
        cpa4(d,        p1 + (size_t)r0 * IMG_W, 4u);
        cpa4(d + 4u,   p1 + (size_t)r1 * IMG_W, 4u);
        cpa4(d + 8u,   p2 + (size_t)r0 * IMG_W, 4u);
        cpa4(d + 12u,  p2 + (size_t)r1 * IMG_W, 4u);
        if (hhalo) {
            const uint32_t e = sbh + (uint32_t)j * PSTR;
            cpa4(e,        p1 + (size_t)r0 * IMG_W + hd, hsz);
            cpa4(e + 4u,   p1 + (size_t)r1 * IMG_W + hd, hsz);
            cpa4(e + 8u,   p2 + (size_t)r0 * IMG_W + hd, hsz);
            cpa4(e + 12u,  p2 + (size_t)r1 * IMG_W + hd, hsz);
        }
    }
    CP_COMMIT();
    CP_WAIT(1);
    __syncthreads();

    // ---------- prime horizontal: 5 pairs (slot 2) -> ring 0..9 ----------
    {
        const float4* swp2 = &sab4[2][0][0];
        #pragma unroll
        for (int i = 0; i < 5; ++i) {
            u64 h1, h2, h3a, h3b, h5;
            {
                const float4 t4 = swp2[i * ECOLS + tid];
                const u64 A = *(const u64*)&t4.x;
                const u64 B = *(const u64*)&t4.z;
                const u64 w = KW2(0);
                const u64 ta = mul2(w, A);
                const u64 tb = mul2(w, B);
                h1 = ta; h2 = tb;
                h3a = mul2(ta, A); h3b = mul2(tb, B); h5 = mul2(ta, B);
            }
            #pragma unroll
            for (int k = 1; k < 11; ++k) {
                const float4 t4 = swp2[i * ECOLS + tid + k];
                const u64 A = *(const u64*)&t4.x;
                const u64 B = *(const u64*)&t4.z;
                const u64 w = KW2(k);
                const u64 ta = mul2(w, A);
                const u64 tb = mul2(w, B);
                h1 = add2(h1, ta);
                h2 = add2(h2, tb);
                h3a = fma2(ta, A, h3a);
                h3b = fma2(tb, B, h3b);
                h5 = fma2(ta, B, h5);
            }
            const u64 h3 = add2(h3a, h3b);
            unpack2(h1, v1[2*i], v1[2*i+1]);
            unpack2(h2, v2[2*i], v2[2*i+1]);
            unpack2(h3, v3[2*i], v3[2*i+1]);
            unpack2(h5, v5[2*i], v5[2*i+1]);
        }
    }
    v1[10] = v2[10] = v3[10] = v5[10] = 0.f;
    v1[11] = v2[11] = v3[11] = v5[11] = 0.f;

    // incrementally advanced prefetch pointers (chunk 1 rows start at y0+17)
    const float* q1 = p1 + (size_t)(y0 + CHUNK + 5) * IMG_W;
    const float* q2 = p2 + (size_t)(y0 + CHUNK + 5) * IMG_W;

    // ---------- main loop: 12-row chunks, one barrier each ----------
    for (int c = 0; c < NCHUNKS; ++c) {
        const int rb = c * CHUNK;
        const int slot = c % 3;

        if (c + 1 < NCHUNKS) {
            const int rb2 = rb + CHUNK;
            const uint32_t soff = (uint32_t)((c + 1) % 3) * SSTR;
            if (y0 + rb2 + 16 < IMG_H) {
                // fast path: all rows in-bounds
                #pragma unroll
                for (int j = 0; j < 6; ++j) {
                    const uint32_t d = sbt + soff + (uint32_t)j * PSTR;
                    cpa4(d,        q1 + j * 2048,        4u);
                    cpa4(d + 4u,   q1 + j * 2048 + 1024, 4u);
                    cpa4(d + 8u,   q2 + j * 2048,        4u);
                    cpa4(d + 12u,  q2 + j * 2048 + 1024, 4u);
                }
                if (hhalo) {
                    #pragma unroll
                    for (int j = 0; j < 6; ++j) {
                        const uint32_t e = sbh + soff + (uint32_t)j * PSTR;
                        cpa4(e,        q1 + j * 2048 + hd,        hsz);
                        cpa4(e + 4u,   q1 + j * 2048 + 1024 + hd, hsz);
                        cpa4(e + 8u,   q2 + j * 2048 + hd,        hsz);
                        cpa4(e + 12u,  q2 + j * 2048 + 1024 + hd, hsz);
                    }
                }
            } else {
                #pragma unroll
                for (int j = 0; j < 6; ++j) {
                    if (rb2 + 2 * j < ROWS) {
                        const int r0 = y0 + rb2 + 5 + 2 * j, r1 = r0 + 1;
                        const unsigned sa = (r0 < IMG_H) ? 4u : 0u;
                        const unsigned sbv = (r1 < IMG_H) ? 4u : 0u;
                        const uint32_t d = sbt + soff + (uint32_t)j * PSTR;
                        cpa4(d,        p1 + (size_t)r0 * IMG_W, sa);
                        cpa4(d + 4u,   p1 + (size_t)r1 * IMG_W, sbv);
                        cpa4(d + 8u,   p2 + (size_t)r0 * IMG_W, sa);
                        cpa4(d + 12u,  p2 + (size_t)r1 * IMG_W, sbv);
                        if (hhalo) {
                            const unsigned ha = (r0 < IMG_H) ? hsz : 0u;
                            const unsigned hb = (r1 < IMG_H) ? hsz : 0u;
                            const uint32_t e = sbh + soff + (uint32_t)j * PSTR;
                            cpa4(e,        p1 + (size_t)r0 * IMG_W + hd, ha);
                            cpa4(e + 4u,   p1 + (size_t)r1 * IMG_W + hd, hb);
                            cpa4(e + 8u,   p2 + (size_t)r0 * IMG_W + hd, ha);
                            cpa4(e + 12u,  p2 + (size_t)r1 * IMG_W + hd, hb);
                        }
                    }
                }
            }
            CP_COMMIT();
            CP_WAIT(1);
        } else {
            CP_WAIT(0);
        }
        q1 += CHUNK * IMG_W;
        q2 += CHUNK * IMG_W;
        __syncthreads();

        {
            const float4* swp = &sab4[slot][0][0];
            if (rb + 11 < ROWS) {
                #pragma unroll
                for (int j = 0; j < 6; ++j) { PAIR_COMPUTE(swp, j, 0); }
            } else {
                #pragma unroll
                for (int j = 0; j < 6; ++j) { PAIR_COMPUTE(swp, j, 1); }
            }
        }
    }

    // ---------- reduction + last-block finalize ----------
    #pragma unroll
    for (int o = 16; o; o >>= 1) acc += __shfl_xor_sync(0xffffffffu, acc, o);
    if ((tid & 31) == 0) red[tid >> 5] = acc;
    __syncthreads();
    if (tid == 0) {
        const double t = (double)(red[0] + red[1] + red[2] + red[3]);
        atomicAdd(&g_acc, t);
        __threadfence();
        const unsigned int n = atomicAdd(&g_cnt, 1u);
        if (n == NBLK - 1) {
            const double total = atomicAdd(&g_acc, 0.0);
            out[0] = (float)(1.0 - total / 16777216.0);
            atomicExch((unsigned long long*)&g_acc, 0ull);
            atomicExch(&g_cnt, 0u);
        }
    }
}

extern "C" void kernel_launch(void* const* d_in, const int* in_sizes, int n_in,
                              void* d_out, int out_size) {
    const float* img1 = (const float*)d_in[0];
    const float* img2 = (const float*)d_in[1];
    float* out = (float*)d_out;

    dim3 grid(IMG_W / EW, IMG_H / ROWS, 16);  // (8, 8, 16) = 1024 CTAs
    ssim_kernel<<<grid, EW>>>(img1, img2, out);
}

// round 17
// speedup vs baseline: 1.1665x; 1.0013x over previous
#include <cuda_runtime.h>
#include <cstdint>

// SSIM loss, fully fused — horizontal-first separable blur, f32x2 row-pair packing,
// LDS.128 interleaved smem, cp.async triple-buffered pipeline, block barriers.
// Round 17: halo load balanced across warps (lanes 0-4 of warp0 = left, lanes 123-127
// of warp3 = right, hd = ±5) + hoisted halo pointers (immediate-foldable offsets).

#define IMG_H 1024
#define IMG_W 1024
#define EW    128          // blockDim.x == output cols per CTA
#define ROWS  128
#define CHUNK 12
#define NCHUNKS ((ROWS + CHUNK - 1) / CHUNK)      // 11 (last chunk: 8 rows)
#define NBLK  (8 * 8 * 16)                        // 1024
#define ECOLS 138          // 128 + 2*5 halo
#define PSTR  2208u        // pair stride bytes   (138*16)
#define SSTR  13248u       // slot stride bytes   (6*2208)

typedef unsigned long long u64;

__device__ double g_acc = 0.0;
__device__ unsigned int g_cnt = 0u;

__device__ __forceinline__ u64 fma2(u64 a, u64 b, u64 c) {
    u64 d; asm("fma.rn.f32x2 %0, %1, %2, %3;" : "=l"(d) : "l"(a), "l"(b), "l"(c)); return d;
}
__device__ __forceinline__ u64 mul2(u64 a, u64 b) {
    u64 d; asm("mul.rn.f32x2 %0, %1, %2;" : "=l"(d) : "l"(a), "l"(b)); return d;
}
__device__ __forceinline__ u64 add2(u64 a, u64 b) {
    u64 d; asm("add.rn.f32x2 %0, %1, %2;" : "=l"(d) : "l"(a), "l"(b)); return d;
}
__device__ __forceinline__ u64 sub2(u64 a, u64 b) {
    u64 d; asm("sub.rn.f32x2 %0, %1, %2;" : "=l"(d) : "l"(a), "l"(b)); return d;
}
__device__ __forceinline__ u64 pack2(float lo, float hi) {
    u64 d; asm("mov.b64 %0, {%1, %2};" : "=l"(d) : "f"(lo), "f"(hi)); return d;
}
__device__ __forceinline__ void unpack2(u64 v, float& lo, float& hi) {
    asm("mov.b64 {%0, %1}, %2;" : "=f"(lo), "=f"(hi) : "l"(v));
}
__device__ __forceinline__ void cpa4(uint32_t dst, const float* src, unsigned sz) {
    asm volatile("cp.async.ca.shared.global [%0], [%1], 4, %2;"
                 :: "r"(dst), "l"(src), "r"(sz));
}
#define CP_COMMIT() asm volatile("cp.async.commit_group;" ::: "memory")
#define CP_WAIT(n)  asm volatile("cp.async.wait_group %0;" :: "n"(n) : "memory")

// per-pair compute; GUARD is 0/1 literal. Reads sab4 flat: [slot][j*138 + tid + k].
#define PAIR_COMPUTE(SWP, J, GUARD) do {                                            \
  if (!(GUARD) || (rb + 2 * (J) < ROWS)) {                                          \
    u64 h1, h2, h3a, h3b, h5;                                                       \
    {                                                                               \
      const float4 t4 = (SWP)[(J) * ECOLS + tid];                                   \
      const u64 A = *(const u64*)&t4.x;                                             \
      const u64 B = *(const u64*)&t4.z;                                             \
      const u64 w = KW2(0);                                                         \
      const u64 ta = mul2(w, A);                                                    \
      const u64 tb = mul2(w, B);                                                    \
      h1 = ta; h2 = tb;                                                             \
      h3a = mul2(ta, A); h3b = mul2(tb, B); h5 = mul2(ta, B);                       \
    }                                                                               \
    _Pragma("unroll")                                                               \
    for (int k = 1; k < 11; ++k) {                                                  \
      const float4 t4 = (SWP)[(J) * ECOLS + tid + k];                               \
      const u64 A = *(const u64*)&t4.x;                                             \
      const u64 B = *(const u64*)&t4.z;                                             \
      const u64 w = KW2(k);                                                         \
      const u64 ta = mul2(w, A);                                                    \
      const u64 tb = mul2(w, B);                                                    \
      h1 = add2(h1, ta);                                                            \
      h2 = add2(h2, tb);                                                            \
      h3a = fma2(ta, A, h3a);                                                       \
      h3b = fma2(tb, B, h3b);                                                       \
      h5 = fma2(ta, B, h5);                                                         \
    }                                                                               \
    const u64 h3 = add2(h3a, h3b);                                                  \
    unpack2(h1, v1[(2*(J)+10)%12], v1[(2*(J)+11)%12]);                              \
    unpack2(h2, v2[(2*(J)+10)%12], v2[(2*(J)+11)%12]);                              \
    unpack2(h3, v3[(2*(J)+10)%12], v3[(2*(J)+11)%12]);                              \
    unpack2(h5, v5[(2*(J)+10)%12], v5[(2*(J)+11)%12]);                              \
    float m1q0, m2q0, m3q0, m5q0, m1q1, m2q1, m3q1, m5q1;                           \
    { float m1=0.f, m2=0.f, m3=0.f, m5=0.f;                                         \
      _Pragma("unroll")                                                             \
      for (int d = 0; d < 11; ++d) {                                                \
        const int s = (2*(J) + d) % 12;                                             \
        m1 = fmaf(KW[d], v1[s], m1); m2 = fmaf(KW[d], v2[s], m2);                   \
        m3 = fmaf(KW[d], v3[s], m3); m5 = fmaf(KW[d], v5[s], m5); }                 \
      m1q0=m1; m2q0=m2; m3q0=m3; m5q0=m5; }                                         \
    { float m1=0.f, m2=0.f, m3=0.f, m5=0.f;                                         \
      _Pragma("unroll")                                                             \
      for (int d = 0; d < 11; ++d) {                                                \
        const int s = (2*(J) + 1 + d) % 12;                                         \
        m1 = fmaf(KW[d], v1[s], m1); m2 = fmaf(KW[d], v2[s], m2);                   \
        m3 = fmaf(KW[d], v3[s], m3); m5 = fmaf(KW[d], v5[s], m5); }                 \
      m1q1=m1; m2q1=m2; m3q1=m3; m5q1=m5; }                                         \
    const u64 M1 = pack2(m1q0, m1q1), M2 = pack2(m2q0, m2q1);                       \
    const u64 M3 = pack2(m3q0, m3q1), M5 = pack2(m5q0, m5q1);                       \
    const u64 MU12 = mul2(M1, M2);                                                  \
    const u64 T    = add2(mul2(M1, M1), mul2(M2, M2));                              \
    const u64 NUM  = mul2(fma2(TW2, MU12, C1V), fma2(TW2, sub2(M5, MU12), C2V));    \
    const u64 DEN  = mul2(add2(T, C1V), add2(sub2(M3, T), C2V));                    \
    float n0, n1, d0, d1; unpack2(NUM, n0, n1); unpack2(DEN, d0, d1);               \
    acc += __fdividef(fmaf(n0, d1, n1 * d0), d0 * d1);                              \
  } } while (0)

__global__ __launch_bounds__(EW, 5) void ssim_kernel(const float* __restrict__ img1,
                                                     const float* __restrict__ img2,
                                                     float* __restrict__ out) {
    const float KW[11] = {
        0.0010283853f, 0.0075987626f, 0.0360007730f, 0.1093606900f,
        0.2130055300f, 0.2660117200f, 0.2130055300f, 0.1093606900f,
        0.0360007730f, 0.0075987626f, 0.0010283853f
    };
    u64 kw2[6];
    #pragma unroll
    for (int k = 0; k < 6; ++k) kw2[k] = pack2(KW[k], KW[k]);
#define KW2(k) kw2[(k) < 6 ? (k) : 10 - (k)]

    const unsigned c1b = __float_as_uint(0.0001f);
    const unsigned c2b = __float_as_uint(0.0009f);
    const unsigned twb = __float_as_uint(2.0f);
    const u64 C1V = ((u64)c1b << 32) | c1b;
    const u64 C2V = ((u64)c2b << 32) | c2b;
    const u64 TW2 = ((u64)twb << 32) | twb;

    const int tid = threadIdx.x;
    const size_t base = (size_t)blockIdx.z * (size_t)(IMG_H * IMG_W);
    const int y0  = blockIdx.y * ROWS;
    const int col = blockIdx.x * EW + tid;           // always in [0, 1023]
    const float* p1 = img1 + base + col;
    const float* p2 = img2 + base + col;

    // halo, balanced across warps:
    //   tid < 5    -> left halo,  ecol = tid,       hd = -5  (warp 0, 5 lanes)
    //   tid >= 123 -> right halo, ecol = tid + 10,  hd = +5  (warp 3, 5 lanes)
    const bool hhalo = (tid < 5) || (tid >= 123);
    const int  hd    = (tid < 5) ? -5 : 5;
    const int  hcol  = col + hd;
    const unsigned hsz = (hhalo && hcol >= 0 && hcol < IMG_W) ? 4u : 0u;
    const uint32_t hecol = (tid < 5) ? (uint32_t)tid : (uint32_t)(tid + 10);
    const float* ph1 = p1 + hd;
    const float* ph2 = p2 + hd;

    __shared__ float4 sab4[3][6][ECOLS];   // interleaved {a_r0,a_r1,b_r0,b_r1}: ~39 KB
    __shared__ float red[4];

    uint32_t sb;
    asm("{ .reg .u64 t; cvta.to.shared.u64 t, %1; cvt.u32.u64 %0, t; }"
        : "=r"(sb) : "l"((void*)&sab4[0][0][0]));
    const uint32_t sbt = sb + (uint32_t)(tid + 5) * 16u;   // main ecol = tid+5
    const uint32_t sbh = sb + hecol * 16u;                 // halo ecol

    float v1[12], v2[12], v3[12], v5[12];
    float acc = 0.f;

    // ---------- issue prime (5 pairs -> slot 2) and chunk 0 (6 pairs -> slot 0) ----------
    #pragma unroll
    for (int i = 0; i < 5; ++i) {
        const int r0 = y0 - 5 + 2 * i, r1 = r0 + 1;
        const unsigned sa = (r0 >= 0) ? 4u : 0u;
        const unsigned sbv = (r1 >= 0) ? 4u : 0u;
        const uint32_t d = sbt + 2u * SSTR + (uint32_t)i * PSTR;
        cpa4(d,        p1 + (size_t)r0 * IMG_W, sa);
        cpa4(d + 4u,   p1 + (size_t)r1 * IMG_W, sbv);
        cpa4(d + 8u,   p2 + (size_t)r0 * IMG_W, sa);
        cpa4(d + 12u,  p2 + (size_t)r1 * IMG_W, sbv);
        if (hhalo) {
            const unsigned ha = (r0 >= 0) ? hsz : 0u;
            const unsigned hb = (r1 >= 0) ? hsz : 0u;
            const uint32_t e = sbh + 2u * SSTR + (uint32_t)i * PSTR;
            cpa4(e,        ph1 + (size_t)r0 * IMG_W, ha);
            cpa4(e + 4u,   ph1 + (size_t)r1 * IMG_W, hb);
            cpa4(e + 8u,   ph2 + (size_t)r0 * IMG_W, ha);
            cpa4(e + 12u,  ph2 + (size_t)r1 * IMG_W, hb);
        }
    }
    CP_COMMIT();
    #pragma unroll
    for (int j = 0; j < 6; ++j) {      // rows y0+5..y0+16; y0 <= 896 -> max 912 < 1024
        const int r0 = y0 + 5 + 2 * j, r1 = r0 + 1;
        const uint32_t d = sbt + (uint32_t)j * PSTR;
        cpa4(d,        p1 + (size_t)r0 * IMG_W, 4u);
        cpa4(d + 4u,   p1 + (size_t)r1 * IMG_W, 4u);
        cpa4(d + 8u,   p2 + (size_t)r0 * IMG_W, 4u);
        cpa4(d + 12u,  p2 + (size_t)r1 * IMG_W, 4u);
        if (hhalo) {
            const uint32_t e = sbh + (uint32_t)j * PSTR;
            cpa4(e,        ph1 + (size_t)r0 * IMG_W, hsz);
            cpa4(e + 4u,   ph1 + (size_t)r1 * IMG_W, hsz);
            cpa4(e + 8u,   ph2 + (size_t)r0 * IMG_W, hsz);
            cpa4(e + 12u,  ph2 + (size_t)r1 * IMG_W, hsz);
        }
    }
    CP_COMMIT();
    CP_WAIT(1);
    __syncthreads();

    // ---------- prime horizontal: 5 pairs (slot 2) -> ring 0..9 ----------
    {
        const float4* swp2 = &sab4[2][0][0];
        #pragma unroll
        for (int i = 0; i < 5; ++i) {
            u64 h1, h2, h3a, h3b, h5;
            {
                const float4 t4 = swp2[i * ECOLS + tid];
                const u64 A = *(const u64*)&t4.x;
                const u64 B = *(const u64*)&t4.z;
                const u64 w = KW2(0);
                const u64 ta = mul2(w, A);
                const u64 tb = mul2(w, B);
                h1 = ta; h2 = tb;
                h3a = mul2(ta, A); h3b = mul2(tb, B); h5 = mul2(ta, B);
            }
            #pragma unroll
            for (int k = 1; k < 11; ++k) {
                const float4 t4 = swp2[i * ECOLS + tid + k];
                const u64 A = *(const u64*)&t4.x;
                const u64 B = *(const u64*)&t4.z;
                const u64 w = KW2(k);
                const u64 ta = mul2(w, A);
                const u64 tb = mul2(w, B);
                h1 = add2(h1, ta);
                h2 = add2(h2, tb);
                h3a = fma2(ta, A, h3a);
                h3b = fma2(tb, B, h3b);
                h5 = fma2(ta, B, h5);
            }
            const u64 h3 = add2(h3a, h3b);
            unpack2(h1, v1[2*i], v1[2*i+1]);
            unpack2(h2, v2[2*i], v2[2*i+1]);
            unpack2(h3, v3[2*i], v3[2*i+1]);
            unpack2(h5, v5[2*i], v5[2*i+1]);
        }
    }
    v1[10] = v2[10] = v3[10] = v5[10] = 0.f;
    v1[11] = v2[11] = v3[11] = v5[11] = 0.f;

    // incrementally advanced prefetch pointers (chunk 1 rows start at y0+17)
    const float* q1 = p1 + (size_t)(y0 + CHUNK + 5) * IMG_W;
    const float* q2 = p2 + (size_t)(y0 + CHUNK + 5) * IMG_W;

    // ---------- main loop: 12-row chunks, one barrier each ----------
    for (int c = 0; c < NCHUNKS; ++c) {
        const int rb = c * CHUNK;
        const int slot = c % 3;

        if (c + 1 < NCHUNKS) {
            const int rb2 = rb + CHUNK;
            const uint32_t soff = (uint32_t)((c + 1) % 3) * SSTR;
            if (y0 + rb2 + 16 < IMG_H) {
                // fast path: all rows in-bounds
                #pragma unroll
                for (int j = 0; j < 6; ++j) {
                    const uint32_t d = sbt + soff + (uint32_t)j * PSTR;
                    cpa4(d,        q1 + j * 2048,        4u);
                    cpa4(d + 4u,   q1 + j * 2048 + 1024, 4u);
                    cpa4(d + 8u,   q2 + j * 2048,        4u);
                    cpa4(d + 12u,  q2 + j * 2048 + 1024, 4u);
                }
                if (hhalo) {
                    const float* hq1 = q1 + hd;    // hoisted: offsets fold to immediates
                    const float* hq2 = q2 + hd;
                    #pragma unroll
                    for (int j = 0; j < 6; ++j) {
                        const uint32_t e = sbh + soff + (uint32_t)j * PSTR;
                        cpa4(e,        hq1 + j * 2048,        hsz);
                        cpa4(e + 4u,   hq1 + j * 2048 + 1024, hsz);
                        cpa4(e + 8u,   hq2 + j * 2048,        hsz);
                        cpa4(e + 12u,  hq2 + j * 2048 + 1024, hsz);
                    }
                }
            } else {
                #pragma unroll
                for (int j = 0; j < 6; ++j) {
                    if (rb2 + 2 * j < ROWS) {
                        const int r0 = y0 + rb2 + 5 + 2 * j, r1 = r0 + 1;
                        const unsigned sa = (r0 < IMG_H) ? 4u : 0u;
                        const unsigned sbv = (r1 < IMG_H) ? 4u : 0u;
                        const uint32_t d = sbt + soff + (uint32_t)j * PSTR;
                        cpa4(d,        p1 + (size_t)r0 * IMG_W, sa);
                        cpa4(d + 4u,   p1 + (size_t)r1 * IMG_W, sbv);
                        cpa4(d + 8u,   p2 + (size_t)r0 * IMG_W, sa);
                        cpa4(d + 12u,  p2 + (size_t)r1 * IMG_W, sbv);
                        if (hhalo) {
                            const unsigned ha = (r0 < IMG_H) ? hsz : 0u;
                            const unsigned hb = (r1 < IMG_H) ? hsz : 0u;
                            const uint32_t e = sbh + soff + (uint32_t)j * PSTR;
                            cpa4(e,        ph1 + (size_t)r0 * IMG_W, ha);
                            cpa4(e + 4u,   ph1 + (size_t)r1 * IMG_W, hb);
                            cpa4(e + 8u,   ph2 + (size_t)r0 * IMG_W, ha);
                            cpa4(e + 12u,  ph2 + (size_t)r1 * IMG_W, hb);
                        }
                    }
                }
            }
            CP_COMMIT();
            CP_WAIT(1);
        } else {
            CP_WAIT(0);
        }
        q1 += CHUNK * IMG_W;
        q2 += CHUNK * IMG_W;
        __syncthreads();

        {
            const float4* swp = &sab4[slot][0][0];
            if (rb + 11 < ROWS) {
                #pragma unroll
                for (int j = 0; j < 6; ++j) { PAIR_COMPUTE(swp, j, 0); }
            } else {
                #pragma unroll
                for (int j = 0; j < 6; ++j) { PAIR_COMPUTE(swp, j, 1); }
            }
        }
    }

    // ---------- reduction + last-block finalize ----------
    #pragma unroll
    for (int o = 16; o; o >>= 1) acc += __shfl_xor_sync(0xffffffffu, acc, o);
    if ((tid & 31) == 0) red[tid >> 5] = acc;
    __syncthreads();
    if (tid == 0) {
        const double t = (double)(red[0] + red[1] + red[2] + red[3]);
        atomicAdd(&g_acc, t);
        __threadfence();
        const unsigned int n = atomicAdd(&g_cnt, 1u);
        if (n == NBLK - 1) {
            const double total = atomicAdd(&g_acc, 0.0);
            out[0] = (float)(1.0 - total / 16777216.0);
            atomicExch((unsigned long long*)&g_acc, 0ull);
            atomicExch(&g_cnt, 0u);
        }
    }
}

extern "C" void kernel_launch(void* const* d_in, const int* in_sizes, int n_in,
                              void* d_out, int out_size) {
    const float* img1 = (const float*)d_in[0];
    const float* img2 = (const float*)d_in[1];
    float* out = (float*)d_out;

    dim3 grid(IMG_W / EW, IMG_H / ROWS, 16);  // (8, 8, 16) = 1024 CTAs
    ssim_kernel<<<grid, EW>>>(img1, img2, out);
}